// round 17
// baseline (speedup 1.0000x reference)
#include <cuda_runtime.h>
#include <cstdint>

#define B_ 4
#define C_ 64
#define N_ 8192
#define K_ 16
#define OUT_ 128
#define TILE_N 64         // nodes per block
#define SUB_N 32          // nodes per pipeline sub-tile
#define H_STRIDE 36       // padded row stride for H in smem (floats)

// Scratch (no cudaMalloc allowed): transposed x [b][n][c] and permuted-transposed W [row][o]
__device__ float g_xT[B_ * N_ * C_];          // 8 MB
__device__ float g_WT[OUT_ * 2 * C_];         // 64 KB

// ---------------------------------------------------------------------------
// Transpose x (B,C,N) -> xT (B,N,C). Tile = 32 c x 128 n, fully float4 on both
// global sides; smem row stride 132 floats.
// ---------------------------------------------------------------------------
__global__ __launch_bounds__(256)
void transpose_x_kernel(const float* __restrict__ x) {
    __shared__ float s[32 * 132];
    const int b  = blockIdx.z;
    const int c0 = blockIdx.y * 32;
    const int n0 = blockIdx.x * 128;
    const int tid = threadIdx.x;

#pragma unroll
    for (int p = 0; p < 4; ++p) {
        const int idx = tid + p * 256;          // 1024 float4 loads
        const int c   = idx >> 5;               // 0..31
        const int n4  = idx & 31;               // 0..31 (float4 index over 128 n)
        const float4 v = ((const float4*)(x + ((b * C_ + c0 + c) * (size_t)N_ + n0)))[n4];
        ((float4*)(s + c * 132))[n4] = v;
    }
    __syncthreads();
#pragma unroll
    for (int p = 0; p < 4; ++p) {
        const int idx = tid + p * 256;          // 1024 float4 stores
        const int n   = idx >> 3;               // 0..127
        const int c4  = idx & 7;                // float4 index over 32 c
        float4 v;
        v.x = s[(4 * c4 + 0) * 132 + n];
        v.y = s[(4 * c4 + 1) * 132 + n];
        v.z = s[(4 * c4 + 2) * 132 + n];
        v.w = s[(4 * c4 + 3) * 132 + n];
        ((float4*)(g_xT + (b * (size_t)N_ + n0 + n) * C_ + c0))[c4] = v;
    }
}

// ---------------------------------------------------------------------------
// Transpose + permute W (128 x 128) -> g_WT[row][o]:
// reference interleaves h[2c]=x_c, h[2c+1]=e_c; map even c2 -> row c2/2 (x part),
// odd c2 -> row 64 + c2/2 (e part).
// ---------------------------------------------------------------------------
__global__ void transpose_w_kernel(const float* __restrict__ W) {
    __shared__ float t[32][33];
    const int c0 = blockIdx.y * 32;
    const int o0 = blockIdx.x * 32;
    const int tx = threadIdx.x, ty = threadIdx.y;
#pragma unroll
    for (int i = 0; i < 32; i += 8)
        t[ty + i][tx] = W[(o0 + ty + i) * (2 * C_) + c0 + tx];
    __syncthreads();
#pragma unroll
    for (int i = 0; i < 32; i += 8) {
        const int c   = c0 + ty + i;
        const int row = (c & 1) ? (C_ + (c >> 1)) : (c >> 1);
        g_WT[row * OUT_ + o0 + tx] = t[tx][ty + i];
    }
}

// ---------------------------------------------------------------------------
// Producer: one warp gathers 8 nodes of a 32-node sub-tile into Hb.
// Lane l covers channels {2l, 2l+1} via float2 (256B coalesced row reads from
// L2-resident xT). Indices distributed by shuffle.
// ---------------------------------------------------------------------------
__device__ __forceinline__ void gather_subtile(
    float* __restrict__ Hb, const float2* __restrict__ xTb,
    const int* __restrict__ ej, const int* __restrict__ ei,
    int n0, int w, int lane)
{
    for (int r = 0; r < 8; ++r) {
        const int nl = w * 8 + r;
        const int n  = n0 + nl;
        const int v  = (lane < 16) ? ej[n * K_ + lane] : ei[n * K_ + (lane - 16)];
        float mx = -3.0e38f, my = -3.0e38f;
#pragma unroll
        for (int k = 0; k < 16; ++k) {
            const int jx = __shfl_sync(0xffffffffu, v, k);
            const int ix = __shfl_sync(0xffffffffu, v, k + 16);
            const float2 aj = xTb[jx * 32 + lane];
            const float2 ai = xTb[ix * 32 + lane];
            mx = fmaxf(mx, aj.x - ai.x);
            my = fmaxf(my, aj.y - ai.y);
        }
        const float2 xv = xTb[n * 32 + lane];
        Hb[(2 * lane)           * H_STRIDE + nl] = xv.x;   // x rows 0..63
        Hb[(2 * lane + 1)       * H_STRIDE + nl] = xv.y;
        Hb[(C_ + 2 * lane)      * H_STRIDE + nl] = mx;     // e rows 64..127
        Hb[(C_ + 2 * lane + 1)  * H_STRIDE + nl] = my;
    }
}

// ---------------------------------------------------------------------------
// Consumer: 128 threads compute out[128 o][32 n] = W^T(128x128) * H(128x32).
// Thread tile: 8 outputs x 4 nodes; accumulators packed as f32x2 over o-pairs.
// W pairs come pre-packed from ulonglong2 LDS.128. NOTE: one W row = 128
// floats = 32 ulonglong2 -> row stride is c*32 (this was the R15 bug: c*16).
// ---------------------------------------------------------------------------
__device__ __forceinline__ void gemm_epi(
    const float* __restrict__ W_s, const float* __restrict__ Hb,
    const float* __restrict__ b_s, float* __restrict__ outB,
    int n_off, int og, int ng)
{
    unsigned long long acc[4][4];
#pragma unroll
    for (int p = 0; p < 4; ++p)
#pragma unroll
        for (int i = 0; i < 4; ++i) acc[p][i] = 0ull;

    const ulonglong2* W2 = (const ulonglong2*)W_s;
#pragma unroll 4
    for (int c = 0; c < 128; ++c) {
        const ulonglong2 u0 = W2[c * 32 + og * 2];       // outputs og*8 + 0..3 (2 pairs)
        const ulonglong2 u1 = W2[c * 32 + og * 2 + 1];   // outputs og*8 + 4..7 (2 pairs)
        const float4 h = *(const float4*)(Hb + c * H_STRIDE + ng * 4);
        unsigned long long hp[4];
        asm("mov.b64 %0, {%1, %1};" : "=l"(hp[0]) : "f"(h.x));
        asm("mov.b64 %0, {%1, %1};" : "=l"(hp[1]) : "f"(h.y));
        asm("mov.b64 %0, {%1, %1};" : "=l"(hp[2]) : "f"(h.z));
        asm("mov.b64 %0, {%1, %1};" : "=l"(hp[3]) : "f"(h.w));
#pragma unroll
        for (int i = 0; i < 4; ++i) {
            asm("fma.rn.f32x2 %0, %1, %2, %0;" : "+l"(acc[0][i]) : "l"(u0.x), "l"(hp[i]));
            asm("fma.rn.f32x2 %0, %1, %2, %0;" : "+l"(acc[1][i]) : "l"(u0.y), "l"(hp[i]));
            asm("fma.rn.f32x2 %0, %1, %2, %0;" : "+l"(acc[2][i]) : "l"(u1.x), "l"(hp[i]));
            asm("fma.rn.f32x2 %0, %1, %2, %0;" : "+l"(acc[3][i]) : "l"(u1.y), "l"(hp[i]));
        }
    }

    // epilogue: bias + relu, float4 stores (8 lanes per o-row cover 128B)
#pragma unroll
    for (int p = 0; p < 4; ++p) {
        float lo[4], hi[4];
#pragma unroll
        for (int i = 0; i < 4; ++i)
            asm("mov.b64 {%0, %1}, %2;" : "=f"(lo[i]), "=f"(hi[i]) : "l"(acc[p][i]));
        const int oe = og * 8 + 2 * p;
        const float be = b_s[oe], bo = b_s[oe + 1];
        float4 re, ro;
        re.x = fmaxf(lo[0] + be, 0.f); re.y = fmaxf(lo[1] + be, 0.f);
        re.z = fmaxf(lo[2] + be, 0.f); re.w = fmaxf(lo[3] + be, 0.f);
        ro.x = fmaxf(hi[0] + bo, 0.f); ro.y = fmaxf(hi[1] + bo, 0.f);
        ro.z = fmaxf(hi[2] + bo, 0.f); ro.w = fmaxf(hi[3] + bo, 0.f);
        *(float4*)(outB + (size_t)oe * N_ + n_off + ng * 4)       = re;
        *(float4*)(outB + (size_t)(oe + 1) * N_ + n_off + ng * 4) = ro;
    }
}

// ---------------------------------------------------------------------------
// Main fused kernel: warp-specialized pipeline per 64-node tile.
//   warps 0-3: gather (L2 bound)      warps 4-7: GEMM (fma bound)
//   stage 0: gather sub0 -> H0   || consumers stage W + bias
//   stage 1: gather sub1 -> H1   || GEMM+epi on H0
//   stage 2:                        GEMM+epi on H1
// ---------------------------------------------------------------------------
__global__ __launch_bounds__(256, 2)
void mrconv_main(const int* __restrict__ edge,
                 const float* __restrict__ bias,
                 float* __restrict__ out) {
    extern __shared__ float smem[];
    float* W_s = smem;                               // 128*128 floats (64 KB)
    float* H0  = smem + OUT_ * 128;                  // 128*36 floats
    float* H1  = H0 + 128 * H_STRIDE;                // 128*36 floats
    float* b_s = H1 + 128 * H_STRIDE;                // 128 floats

    const int tid    = threadIdx.x;
    const int w      = tid >> 5;
    const int lane   = tid & 31;
    const int b      = blockIdx.x >> 7;              // 128 tiles per batch
    const int n_base = (blockIdx.x & 127) * TILE_N;

    const float2* xTb = (const float2*)g_xT + b * (N_ * C_ / 2);
    const int* ej = edge + (b * N_) * K_;            // edge_index[0] = j
    const int* ei = edge + (B_ * N_ + b * N_) * K_;  // edge_index[1] = i
    float* outB = out + (b * OUT_) * (size_t)N_;

    // ---- stage 0 ----
    if (w < 4) {
        gather_subtile(H0, xTb, ej, ei, n_base, w, lane);
    } else {
        const int t = tid - 128;
        const float4* src = (const float4*)g_WT;
        float4*       dst = (float4*)W_s;
#pragma unroll
        for (int i = t; i < OUT_ * 32; i += 128) dst[i] = src[i];
        b_s[t] = bias[t];
    }
    __syncthreads();

    // ---- stage 1 ----
    if (w < 4) {
        gather_subtile(H1, xTb, ej, ei, n_base + SUB_N, w, lane);
    } else {
        const int t = tid - 128;
        gemm_epi(W_s, H0, b_s, outB, n_base, t >> 3, t & 7);
    }
    __syncthreads();

    // ---- stage 2 ----
    if (w >= 4) {
        const int t = tid - 128;
        gemm_epi(W_s, H1, b_s, outB, n_base + SUB_N, t >> 3, t & 7);
    }
}

// ---------------------------------------------------------------------------
extern "C" void kernel_launch(void* const* d_in, const int* in_sizes, int n_in,
                              void* d_out, int out_size) {
    const float* x    = (const float*)d_in[0];
    const int*   edge = (const int*)d_in[1];
    const float* W    = (const float*)d_in[2];
    const float* bias = (const float*)d_in[3];
    float*       out  = (float*)d_out;

    transpose_x_kernel<<<dim3(N_ / 128, C_ / 32, B_), 256>>>(x);
    transpose_w_kernel<<<dim3(OUT_ / 32, (2 * C_) / 32, 1), dim3(32, 8)>>>(W);

    const int smem_bytes = (OUT_ * 128 + 2 * 128 * H_STRIDE + 128) * (int)sizeof(float);
    cudaFuncSetAttribute(mrconv_main, cudaFuncAttributeMaxDynamicSharedMemorySize, smem_bytes);
    mrconv_main<<<(B_ * N_) / TILE_N, 256, smem_bytes>>>(edge, bias, out);
}